// round 14
// baseline (speedup 1.0000x reference)
#include <cuda_runtime.h>
#include <cuda_bf16.h>
#include <math.h>
#include <stdint.h>

#define NN 100000
#define DD 128
#define KE 16
#define NB 782            // ceil(NN/128)
#define DTS 0.1f
#define SP 132            // fp32 row stride (floats) for dh/yn buffer
#define UP 20             // U row stride (floats): kb offsets stay 16B-aligned
#define SA 136            // bf16 row stride for MMA tiles (272 B, LDSM conflict-free)
#define THR 512

// ---------------- global scratch (no allocations allowed) ----------------
__device__ float g_Y[NN * DD];
__device__ float g_acc[NN * DD];
__device__ float g_part[NB * KE * DD];
__device__ float g_G[KE * DD];
__device__ float g_tmod[DD];            // tanh(t*Wt + bt), per stage
// bf16 hi/lo weight images, row-major [d][k]: [0]=Wr, [1]=Wz, [2]=Wc
__device__ __align__(16) __nv_bfloat16 g_Wh[3][DD * DD];
__device__ __align__(16) __nv_bfloat16 g_Wl[3][DD * DD];

// ---------------- smem byte offsets ----------------
#define OFF_AHI 0
#define OFF_ALO 34816
#define OFF_W1H 69632
#define OFF_W1L 104448
#define OFF_W2H 139264
#define OFF_W2L 174080
#define OFF_SU  208896     // 128*20*4 = 10240
#define OFF_SG  219136     // 16*132*4 = 8448
#define SMEM_BYTES 227584

// fast transcendentals via MUFU path (err ~1e-6; tolerance margin ~1000x)
__device__ __forceinline__ float sigm(float x) {
    return __fdividef(1.0f, 1.0f + __expf(-x));
}
__device__ __forceinline__ float tanh_fast(float x) {
    float e = __expf(2.0f * x);
    return 1.0f - __fdividef(2.0f, e + 1.0f);
}
__device__ __forceinline__ float bfhi(float a) {
    return __bfloat162float(__float2bfloat16(a));
}
__device__ __forceinline__ unsigned pack2(float a, float b) {
    __nv_bfloat162 t = __floats2bfloat162_rn(a, b);
    return *reinterpret_cast<unsigned*>(&t);
}
// reconstruct fp32 pair (cols c0, c0+1) from hi/lo bf16 tiles
__device__ __forceinline__ float2 yrec(const char* aHi, const char* aLo,
                                       int row, int c0) {
    const __nv_bfloat162 h =
        *reinterpret_cast<const __nv_bfloat162*>(aHi + (row * SA + c0) * 2);
    const __nv_bfloat162 l =
        *reinterpret_cast<const __nv_bfloat162*>(aLo + (row * SA + c0) * 2);
    float2 fh = __bfloat1622float2(h);
    float2 fl = __bfloat1622float2(l);
    return make_float2(fh.x + fl.x, fh.y + fl.y);
}
__device__ __forceinline__ uint32_t smem_u32(const void* p) {
    uint32_t a;
    asm("{ .reg .u64 t; cvta.to.shared.u64 t, %1; cvt.u32.u64 %0, t; }"
        : "=r"(a) : "l"(p));
    return a;
}
__device__ __forceinline__ void ldsm4(uint32_t a[4], uint32_t addr) {
    asm volatile("ldmatrix.sync.aligned.m8n8.x4.shared.b16 {%0,%1,%2,%3}, [%4];"
                 : "=r"(a[0]), "=r"(a[1]), "=r"(a[2]), "=r"(a[3]) : "r"(addr));
}
__device__ __forceinline__ void ldsm2(uint32_t b[2], uint32_t addr) {
    asm volatile("ldmatrix.sync.aligned.m8n8.x2.shared.b16 {%0,%1}, [%2];"
                 : "=r"(b[0]), "=r"(b[1]) : "r"(addr));
}
__device__ __forceinline__ void mma16816(float c[4], const uint32_t a[4],
                                         const uint32_t b[2]) {
    asm volatile(
        "mma.sync.aligned.m16n8k16.row.col.f32.bf16.bf16.f32 "
        "{%0,%1,%2,%3}, {%4,%5,%6,%7}, {%8,%9}, {%0,%1,%2,%3};"
        : "+f"(c[0]), "+f"(c[1]), "+f"(c[2]), "+f"(c[3])
        : "r"(a[0]), "r"(a[1]), "r"(a[2]), "r"(a[3]), "r"(b[0]), "r"(b[1]));
}

// split-precision 128x128x128 warp GEMM: acc += A*W^T via hi*hi + hi*lo + lo*hi
__device__ __forceinline__ void gemm3(uint32_t aH, uint32_t aL, uint32_t wH,
                                      uint32_t wL, int wm, int wn, int lid,
                                      float acc[2][4][4]) {
    const int arow = lid & 15;
    const int akoff = (lid >> 4) << 3;
    const int brow = lid & 7;
    const int bkoff = ((lid >> 3) & 1) << 3;
#pragma unroll 1
    for (int ks = 0; ks < 8; ks++) {
        const int kb = ks * 16;
        uint32_t Ah[2][4], Al[2][4];
#pragma unroll
        for (int mi = 0; mi < 2; mi++) {
            uint32_t off = (uint32_t)(((wm + mi * 16 + arow) * SA + kb + akoff) * 2);
            ldsm4(Ah[mi], aH + off);
            ldsm4(Al[mi], aL + off);
        }
#pragma unroll
        for (int nj = 0; nj < 4; nj++) {
            uint32_t boff = (uint32_t)(((wn + nj * 8 + brow) * SA + kb + bkoff) * 2);
            uint32_t Bh[2], Bl[2];
            ldsm2(Bh, wH + boff);
            ldsm2(Bl, wL + boff);
#pragma unroll
            for (int mi = 0; mi < 2; mi++) {
                mma16816(acc[mi][nj], Ah[mi], Bh);
                mma16816(acc[mi][nj], Ah[mi], Bl);
                mma16816(acc[mi][nj], Al[mi], Bh);
            }
        }
    }
}

// stage weight image w (0=Wr, 1=Wz, 2=Wc) into smem hi/lo tiles
__device__ __forceinline__ void stage_w(char* wHi, char* wLo, int w, int tx) {
    const float4* sh = reinterpret_cast<const float4*>(g_Wh[w]);
    const float4* sl = reinterpret_cast<const float4*>(g_Wl[w]);
#pragma unroll
    for (int it = 0; it < 4; it++) {
        int i = tx + THR * it;
        int r = i >> 4, sg = i & 15;
        *reinterpret_cast<float4*>(wHi + (r * SA + sg * 8) * 2) = sh[i];
        *reinterpret_cast<float4*>(wLo + (r * SA + sg * 8) * 2) = sl[i];
    }
}

// ---------------------------------------------------------------------------
__global__ void initcopy_kernel(const float* __restrict__ h0, float* __restrict__ H) {
    int i = blockIdx.x * blockDim.x + threadIdx.x;
    if (i < NN * DD / 4) {
        float4 v = reinterpret_cast<const float4*>(h0)[i];
        reinterpret_cast<float4*>(H)[i] = v;
        reinterpret_cast<float4*>(g_Y)[i] = v;
    }
}

__global__ void wprep_kernel(const float* __restrict__ Wr, const float* __restrict__ Wz,
                             const float* __restrict__ Wc) {
    int idx = blockIdx.x * blockDim.x + threadIdx.x;
    if (idx >= 3 * DD * DD) return;
    int w = idx >> 14, e = idx & 16383;
    const float* W = (w == 0) ? Wr : ((w == 1) ? Wz : Wc);
    float v = W[e];
    __nv_bfloat16 hb = __float2bfloat16(v);
    g_Wh[w][e] = hb;
    g_Wl[w][e] = __float2bfloat16(v - __bfloat162float(hb));
}

__global__ void gpartial0_kernel(const float* __restrict__ U) {
    int tx = threadIdx.x, bid = blockIdx.x;
    int d = tx & 127, kb = (tx >> 7) * 8;
    float f[8];
#pragma unroll
    for (int k = 0; k < 8; k++) f[k] = 0.f;
    int row0 = bid * 128;
    int rmax = min(128, NN - row0);
    for (int r = 0; r < rmax; r++) {
        int n = row0 + r;
        float yv = g_Y[n * DD + d];
#pragma unroll
        for (int k = 0; k < 8; k++) f[k] = fmaf(__ldg(&U[n * KE + kb + k]), yv, f[k]);
    }
#pragma unroll
    for (int k = 0; k < 8; k++) g_part[bid * (KE * DD) + (kb + k) * DD + d] = f[k];
}

// single-kernel reduction of g_part -> g_G + per-stage t_mod precompute.
// grid 64 x 32: thread owns element e, sums 782 partials with 8 fixed-order
// accumulator chains (deterministic).
__global__ void gstage_kernel(const float* __restrict__ Wt,
                              const float* __restrict__ bt, float t) {
    int e = blockIdx.x * 32 + threadIdx.x;   // 0..2047
    float s[8];
#pragma unroll
    for (int c = 0; c < 8; c++) s[c] = 0.f;
    int b = 0;
    for (; b + 8 <= NB; b += 8) {
#pragma unroll
        for (int c = 0; c < 8; c++) s[c] += g_part[(b + c) * (KE * DD) + e];
    }
    for (; b < NB; ++b) s[0] += g_part[b * (KE * DD) + e];
    g_G[e] = ((s[0] + s[1]) + (s[2] + s[3])) + ((s[4] + s[5]) + (s[6] + s[7]));
    if (e < DD) g_tmod[e] = tanh_fast(t * __ldg(&Wt[e]) + __ldg(&bt[e]));
}

// ---------------------------------------------------------------------------
// fused stage kernel: mma.sync bf16x3 GEMMs + gates + RK4 + partial-G.
// No fp32 Y copy: y reconstructed from bf16 hi+lo (err 2^-18). Wz+Wr staged
// together; rY goes into the freed Wr slot; A-region reused as fp32 dh/yn buf.
// ---------------------------------------------------------------------------
__global__ __launch_bounds__(THR, 1) void fused_kernel(
    const float* H, const float* __restrict__ U,
    const float* __restrict__ bz, const float* __restrict__ br,
    const float* __restrict__ bc, const float* __restrict__ mup,
    float* Hout, int mode, float t) {
    extern __shared__ char sb[];
    char* aHi = sb + OFF_AHI;
    char* aLo = sb + OFF_ALO;
    char* w1Hi = sb + OFF_W1H;
    char* w1Lo = sb + OFF_W1L;
    char* w2Hi = sb + OFF_W2H;
    char* w2Lo = sb + OFF_W2L;
    float* sU = (float*)(sb + OFF_SU);
    float* sG = (float*)(sb + OFF_SG);
    float* sYd = (float*)(sb + OFF_AHI);   // fp32 dh/yn buffer (reuses A region)
    const uint32_t baseU = smem_u32(sb);
    const uint32_t aHiU = baseU + OFF_AHI, aLoU = baseU + OFF_ALO;
    const uint32_t w1HiU = baseU + OFF_W1H, w1LoU = baseU + OFF_W1L;
    const uint32_t w2HiU = baseU + OFF_W2H, w2LoU = baseU + OFF_W2L;

    const int tx = threadIdx.x;
    const int w = tx >> 5, lid = tx & 31;
    const int wm = (w >> 2) * 32, wn = (w & 3) * 32;
    const int bid = blockIdx.x, row0 = bid * 128;

    // ---- load Y -> aHi/aLo bf16; sU; sG; stage Wz->W1, Wr->W2 ----
#pragma unroll
    for (int it = 0; it < 8; ++it) {
        int idx = tx + THR * it;
        int r = idx >> 5, q = idx & 31;
        int n = row0 + r;
        float4 v = make_float4(0.f, 0.f, 0.f, 0.f);
        if (n < NN) v = reinterpret_cast<const float4*>(g_Y)[n * 32 + q];
        char* p = aHi + (r * SA + q * 4) * 2;
        char* pl = aLo + (r * SA + q * 4) * 2;
        *reinterpret_cast<unsigned*>(p) = pack2(v.x, v.y);
        *reinterpret_cast<unsigned*>(p + 4) = pack2(v.z, v.w);
        *reinterpret_cast<unsigned*>(pl) = pack2(v.x - bfhi(v.x), v.y - bfhi(v.y));
        *reinterpret_cast<unsigned*>(pl + 4) = pack2(v.z - bfhi(v.z), v.w - bfhi(v.w));
    }
#pragma unroll
    for (int it = 0; it < 4; ++it) {
        int idx = tx + THR * it;
        int r = idx >> 4, k = idx & 15;
        int n = row0 + r;
        sU[r * UP + k] = (n < NN) ? __ldg(&U[n * KE + k]) : 0.f;
    }
#pragma unroll
    for (int it = 0; it < 4; ++it) {
        int idx = tx + THR * it;
        int k = idx >> 7, d = idx & 127;
        sG[k * SP + d] = g_G[idx];
    }
    stage_w(w1Hi, w1Lo, 1, tx);   // Wz -> W1
    stage_w(w2Hi, w2Lo, 0, tx);   // Wr -> W2
    __syncthreads();

    // ---- GEMM Z (A x W1) and GEMM R (A x W2), back-to-back ----
    float az[2][4][4], ar[2][4][4];
#pragma unroll
    for (int mi = 0; mi < 2; mi++)
#pragma unroll
        for (int nj = 0; nj < 4; nj++)
#pragma unroll
            for (int c = 0; c < 4; c++) { az[mi][nj][c] = 0.f; ar[mi][nj][c] = 0.f; }
    gemm3(aHiU, aLoU, w1HiU, w1LoU, wm, wn, lid, az);
    gemm3(aHiU, aLoU, w2HiU, w2LoU, wm, wn, lid, ar);

    // gate z; gate r -> rY (y reconstructed from hi/lo)
#pragma unroll
    for (int mi = 0; mi < 2; mi++)
#pragma unroll
        for (int nj = 0; nj < 4; nj++) {
            int c0 = wn + nj * 8 + (lid & 3) * 2;
#pragma unroll
            for (int hh = 0; hh < 2; hh++) {
                int row = wm + mi * 16 + (lid >> 2) + hh * 8;
                float2 y = yrec(aHi, aLo, row, c0);
#pragma unroll
                for (int p = 0; p < 2; p++) {
                    az[mi][nj][hh * 2 + p] =
                        1.0f - sigm(az[mi][nj][hh * 2 + p] + __ldg(&bz[c0 + p]));
                    float rv = sigm(ar[mi][nj][hh * 2 + p] + __ldg(&br[c0 + p]));
                    ar[mi][nj][hh * 2 + p] = rv * (p ? y.y : y.x);
                }
            }
        }
    __syncthreads();   // all GEMM Z/R reads of W1/W2 complete

    // ---- write rY (hi/lo) into W2 region; stage Wc -> W1 ----
#pragma unroll
    for (int mi = 0; mi < 2; mi++)
#pragma unroll
        for (int hh = 0; hh < 2; hh++) {
            int row = wm + mi * 16 + (lid >> 2) + hh * 8;
#pragma unroll
            for (int nj = 0; nj < 4; nj++) {
                int c0 = wn + nj * 8 + (lid & 3) * 2;
                float v0 = ar[mi][nj][hh * 2], v1 = ar[mi][nj][hh * 2 + 1];
                *reinterpret_cast<unsigned*>(w2Hi + (row * SA + c0) * 2) = pack2(v0, v1);
                *reinterpret_cast<unsigned*>(w2Lo + (row * SA + c0) * 2) =
                    pack2(v0 - bfhi(v0), v1 - bfhi(v1));
            }
        }
    stage_w(w1Hi, w1Lo, 2, tx);   // Wc -> W1
    __syncthreads();

    // ---- GEMM C: ac = rY (W2 region as A) x Wc (W1) ----
    float ac[2][4][4];
#pragma unroll
    for (int mi = 0; mi < 2; mi++)
#pragma unroll
        for (int nj = 0; nj < 4; nj++)
#pragma unroll
            for (int c = 0; c < 4; c++) ac[mi][nj][c] = 0.f;
    gemm3(w2HiU, w2LoU, w1HiU, w1LoU, wm, wn, lid, ac);

    // ---- gating + spectral + dh in regs (A/Y tile still intact) ----
    {
        float mu = __ldg(mup);
#pragma unroll
        for (int mi = 0; mi < 2; mi++)
#pragma unroll
            for (int hh = 0; hh < 2; hh++) {
                int row = wm + mi * 16 + (lid >> 2) + hh * 8;
                float u[KE];
                {
                    const float4* up = reinterpret_cast<const float4*>(&sU[row * UP]);
#pragma unroll
                    for (int q = 0; q < 4; q++) {
                        float4 uv = up[q];
                        u[q * 4 + 0] = uv.x; u[q * 4 + 1] = uv.y;
                        u[q * 4 + 2] = uv.z; u[q * 4 + 3] = uv.w;
                    }
                }
#pragma unroll
                for (int nj = 0; nj < 4; nj++) {
                    int c0 = wn + nj * 8 + (lid & 3) * 2;
                    float s0 = 0.f, s1 = 0.f;
#pragma unroll
                    for (int k = 0; k < KE; k++) {
                        float2 g = *reinterpret_cast<const float2*>(&sG[k * SP + c0]);
                        s0 = fmaf(u[k], g.x, s0);
                        s1 = fmaf(u[k], g.y, s1);
                    }
                    float2 y = yrec(aHi, aLo, row, c0);
#pragma unroll
                    for (int p = 0; p < 2; p++) {
                        int d = c0 + p;
                        float yv = p ? y.y : y.x;
                        float sv = p ? s1 : s0;
                        float tmv = __ldg(&g_tmod[d]);
                        float cq = tanh_fast(ac[mi][nj][hh * 2 + p] + __ldg(&bc[d]));
                        float ozv = az[mi][nj][hh * 2 + p];
                        ac[mi][nj][hh * 2 + p] =
                            ozv * (cq + tmv - yv) - mu * (yv - sv);
                    }
                }
            }
    }
    __syncthreads();   // all y reads of A done; A region becomes fp32 dh buffer

    // ---- write dh fp32 into sYd (float2, exclusive slots) ----
#pragma unroll
    for (int mi = 0; mi < 2; mi++)
#pragma unroll
        for (int hh = 0; hh < 2; hh++) {
            int row = wm + mi * 16 + (lid >> 2) + hh * 8;
#pragma unroll
            for (int nj = 0; nj < 4; nj++) {
                int c0 = wn + nj * 8 + (lid & 3) * 2;
                *reinterpret_cast<float2*>(&sYd[row * SP + c0]) =
                    make_float2(ac[mi][nj][hh * 2], ac[mi][nj][hh * 2 + 1]);
            }
        }
    __syncthreads();

    // ---- coalesced RK4 epilogue; Y_next back into sYd for partial-G ----
#pragma unroll
    for (int it = 0; it < 8; ++it) {
        int idx = tx + THR * it;
        int r = idx >> 5, q = idx & 31;
        int n = row0 + r;
        float4 kv = *reinterpret_cast<float4*>(&sYd[r * SP + q * 4]);
        float4 yn = make_float4(0.f, 0.f, 0.f, 0.f);
        if (n < NN) {
            int g = n * 32 + q;
            float4 h4 = reinterpret_cast<const float4*>(H)[g];
            if (mode == 0) {
                reinterpret_cast<float4*>(g_acc)[g] = kv;
                yn.x = fmaf(0.05f, kv.x, h4.x); yn.y = fmaf(0.05f, kv.y, h4.y);
                yn.z = fmaf(0.05f, kv.z, h4.z); yn.w = fmaf(0.05f, kv.w, h4.w);
            } else if (mode < 3) {
                float4 a4 = reinterpret_cast<float4*>(g_acc)[g];
                a4.x += 2.f * kv.x; a4.y += 2.f * kv.y;
                a4.z += 2.f * kv.z; a4.w += 2.f * kv.w;
                reinterpret_cast<float4*>(g_acc)[g] = a4;
                float cy = (mode == 1) ? 0.05f : 0.1f;
                yn.x = fmaf(cy, kv.x, h4.x); yn.y = fmaf(cy, kv.y, h4.y);
                yn.z = fmaf(cy, kv.z, h4.z); yn.w = fmaf(cy, kv.w, h4.w);
            } else {
                float4 a4 = reinterpret_cast<float4*>(g_acc)[g];
                const float c6 = DTS / 6.0f;
                yn.x = fmaf(c6, a4.x + kv.x, h4.x);
                yn.y = fmaf(c6, a4.y + kv.y, h4.y);
                yn.z = fmaf(c6, a4.z + kv.z, h4.z);
                yn.w = fmaf(c6, a4.w + kv.w, h4.w);
                reinterpret_cast<float4*>(Hout)[g] = yn;
            }
            reinterpret_cast<float4*>(g_Y)[g] = yn;
        }
        *reinterpret_cast<float4*>(&sYd[r * SP + q * 4]) = yn;
    }
    __syncthreads();

    // ---- fused partial G for next stage (broadcast u via LDS.128) ----
    {
        int d = tx & 127, kb = (tx >> 7) * 4;
        float4 f = make_float4(0.f, 0.f, 0.f, 0.f);
#pragma unroll 4
        for (int r = 0; r < 128; r++) {
            float yv = sYd[r * SP + d];
            float4 u4 = *reinterpret_cast<const float4*>(&sU[r * UP + kb]);
            f.x = fmaf(u4.x, yv, f.x);
            f.y = fmaf(u4.y, yv, f.y);
            f.z = fmaf(u4.z, yv, f.z);
            f.w = fmaf(u4.w, yv, f.w);
        }
        float* gp = &g_part[bid * (KE * DD)];
        gp[(kb + 0) * DD + d] = f.x;
        gp[(kb + 1) * DD + d] = f.y;
        gp[(kb + 2) * DD + d] = f.z;
        gp[(kb + 3) * DD + d] = f.w;
    }
}

// ---------------------------------------------------------------------------
extern "C" void kernel_launch(void* const* d_in, const int* in_sizes, int n_in,
                              void* d_out, int out_size) {
    const float* h0 = (const float*)d_in[0];
    const float* U  = (const float*)d_in[1];
    const float* Wz = (const float*)d_in[2];
    const float* bz = (const float*)d_in[3];
    const float* Wr = (const float*)d_in[4];
    const float* br = (const float*)d_in[5];
    const float* Wc = (const float*)d_in[6];
    const float* bc = (const float*)d_in[7];
    const float* Wt = (const float*)d_in[8];
    const float* bt = (const float*)d_in[9];
    const float* mu = (const float*)d_in[10];
    float* H = (float*)d_out;

    cudaError_t rc = cudaFuncSetAttribute(
        fused_kernel, cudaFuncAttributeMaxDynamicSharedMemorySize, SMEM_BYTES);
    (void)rc;

    initcopy_kernel<<<(NN * DD / 4 + 255) / 256, 256>>>(h0, H);
    wprep_kernel<<<(3 * DD * DD + 511) / 512, 512>>>(Wr, Wz, Wc);
    gpartial0_kernel<<<NB, 256>>>(U);

    for (int i = 0; i < 10; i++) {
        float tb = (float)i * DTS;
        float ts[4] = {tb, tb + 0.05f, tb + 0.05f, tb + 0.1f};
        for (int s = 0; s < 4; s++) {
            gstage_kernel<<<64, 32>>>(Wt, bt, ts[s]);
            fused_kernel<<<NB, THR, SMEM_BYTES>>>(H, U, bz, br, bc, mu,
                                                  H, s, ts[s]);
        }
    }
}

// round 17
// speedup vs baseline: 1.1144x; 1.1144x over previous
#include <cuda_runtime.h>
#include <cuda_bf16.h>
#include <math.h>
#include <stdint.h>

#define NN 100000
#define DD 128
#define KE 16
#define NB 782            // ceil(NN/128)
#define DTS 0.1f
#define SP 132            // fp32 row stride (floats) for dh/yn buffer
#define UP 20             // U row stride (floats): kb offsets stay 16B-aligned
#define SA 136            // bf16 row stride for MMA tiles (272 B, LDSM conflict-free)
#define THR 512

// ---------------- global scratch (no allocations allowed) ----------------
__device__ float g_Y[NN * DD];
__device__ float g_acc[NN * DD];
__device__ float g_part[NB * KE * DD];
__device__ float g_part2[8 * KE * DD];
__device__ float g_G[KE * DD];
__device__ float g_tmod[DD];            // tanh(t*Wt + bt), per stage
// bf16 hi/lo weight images, row-major [d][k]: [0]=Wr, [1]=Wz, [2]=Wc
__device__ __align__(16) __nv_bfloat16 g_Wh[3][DD * DD];
__device__ __align__(16) __nv_bfloat16 g_Wl[3][DD * DD];

// ---------------- smem byte offsets ----------------
#define OFF_AHI 0
#define OFF_ALO 34816
#define OFF_W1H 69632
#define OFF_W1L 104448
#define OFF_W2H 139264
#define OFF_W2L 174080
#define OFF_SU  208896     // 128*20*4 = 10240
#define OFF_SG  219136     // 16*132*4 = 8448
#define SMEM_BYTES 227584

// fast transcendentals via MUFU path (err ~1e-6; tolerance margin ~1000x)
__device__ __forceinline__ float sigm(float x) {
    return __fdividef(1.0f, 1.0f + __expf(-x));
}
__device__ __forceinline__ float tanh_fast(float x) {
    float e = __expf(2.0f * x);
    return 1.0f - __fdividef(2.0f, e + 1.0f);
}
__device__ __forceinline__ float bfhi(float a) {
    return __bfloat162float(__float2bfloat16(a));
}
__device__ __forceinline__ unsigned pack2(float a, float b) {
    __nv_bfloat162 t = __floats2bfloat162_rn(a, b);
    return *reinterpret_cast<unsigned*>(&t);
}
// reconstruct fp32 pair (cols c0, c0+1) from hi/lo bf16 tiles
__device__ __forceinline__ float2 yrec(const char* aHi, const char* aLo,
                                       int row, int c0) {
    const __nv_bfloat162 h =
        *reinterpret_cast<const __nv_bfloat162*>(aHi + (row * SA + c0) * 2);
    const __nv_bfloat162 l =
        *reinterpret_cast<const __nv_bfloat162*>(aLo + (row * SA + c0) * 2);
    float2 fh = __bfloat1622float2(h);
    float2 fl = __bfloat1622float2(l);
    return make_float2(fh.x + fl.x, fh.y + fl.y);
}
__device__ __forceinline__ uint32_t smem_u32(const void* p) {
    uint32_t a;
    asm("{ .reg .u64 t; cvta.to.shared.u64 t, %1; cvt.u32.u64 %0, t; }"
        : "=r"(a) : "l"(p));
    return a;
}
__device__ __forceinline__ void ldsm4(uint32_t a[4], uint32_t addr) {
    asm volatile("ldmatrix.sync.aligned.m8n8.x4.shared.b16 {%0,%1,%2,%3}, [%4];"
                 : "=r"(a[0]), "=r"(a[1]), "=r"(a[2]), "=r"(a[3]) : "r"(addr));
}
__device__ __forceinline__ void ldsm2(uint32_t b[2], uint32_t addr) {
    asm volatile("ldmatrix.sync.aligned.m8n8.x2.shared.b16 {%0,%1}, [%2];"
                 : "=r"(b[0]), "=r"(b[1]) : "r"(addr));
}
__device__ __forceinline__ void mma16816(float c[4], const uint32_t a[4],
                                         const uint32_t b[2]) {
    asm volatile(
        "mma.sync.aligned.m16n8k16.row.col.f32.bf16.bf16.f32 "
        "{%0,%1,%2,%3}, {%4,%5,%6,%7}, {%8,%9}, {%0,%1,%2,%3};"
        : "+f"(c[0]), "+f"(c[1]), "+f"(c[2]), "+f"(c[3])
        : "r"(a[0]), "r"(a[1]), "r"(a[2]), "r"(a[3]), "r"(b[0]), "r"(b[1]));
}

// split-precision 128x128x128 warp GEMM: acc += A*W^T via hi*hi + hi*lo + lo*hi
__device__ __forceinline__ void gemm3(uint32_t aH, uint32_t aL, uint32_t wH,
                                      uint32_t wL, int wm, int wn, int lid,
                                      float acc[2][4][4]) {
    const int arow = lid & 15;
    const int akoff = (lid >> 4) << 3;
    const int brow = lid & 7;
    const int bkoff = ((lid >> 3) & 1) << 3;
#pragma unroll 1
    for (int ks = 0; ks < 8; ks++) {
        const int kb = ks * 16;
        uint32_t Ah[2][4], Al[2][4];
#pragma unroll
        for (int mi = 0; mi < 2; mi++) {
            uint32_t off = (uint32_t)(((wm + mi * 16 + arow) * SA + kb + akoff) * 2);
            ldsm4(Ah[mi], aH + off);
            ldsm4(Al[mi], aL + off);
        }
#pragma unroll
        for (int nj = 0; nj < 4; nj++) {
            uint32_t boff = (uint32_t)(((wn + nj * 8 + brow) * SA + kb + bkoff) * 2);
            uint32_t Bh[2], Bl[2];
            ldsm2(Bh, wH + boff);
            ldsm2(Bl, wL + boff);
#pragma unroll
            for (int mi = 0; mi < 2; mi++) {
                mma16816(acc[mi][nj], Ah[mi], Bh);
                mma16816(acc[mi][nj], Ah[mi], Bl);
                mma16816(acc[mi][nj], Al[mi], Bh);
            }
        }
    }
}

// stage weight image w (0=Wr, 1=Wz, 2=Wc) into smem hi/lo tiles
__device__ __forceinline__ void stage_w(char* wHi, char* wLo, int w, int tx) {
    const float4* sh = reinterpret_cast<const float4*>(g_Wh[w]);
    const float4* sl = reinterpret_cast<const float4*>(g_Wl[w]);
#pragma unroll
    for (int it = 0; it < 4; it++) {
        int i = tx + THR * it;
        int r = i >> 4, sg = i & 15;
        *reinterpret_cast<float4*>(wHi + (r * SA + sg * 8) * 2) = sh[i];
        *reinterpret_cast<float4*>(wLo + (r * SA + sg * 8) * 2) = sl[i];
    }
}

// ---------------------------------------------------------------------------
__global__ void initcopy_kernel(const float* __restrict__ h0, float* __restrict__ H) {
    int i = blockIdx.x * blockDim.x + threadIdx.x;
    if (i < NN * DD / 4) {
        float4 v = reinterpret_cast<const float4*>(h0)[i];
        reinterpret_cast<float4*>(H)[i] = v;
        reinterpret_cast<float4*>(g_Y)[i] = v;
    }
}

__global__ void wprep_kernel(const float* __restrict__ Wr, const float* __restrict__ Wz,
                             const float* __restrict__ Wc) {
    int idx = blockIdx.x * blockDim.x + threadIdx.x;
    if (idx >= 3 * DD * DD) return;
    int w = idx >> 14, e = idx & 16383;
    const float* W = (w == 0) ? Wr : ((w == 1) ? Wz : Wc);
    float v = W[e];
    __nv_bfloat16 hb = __float2bfloat16(v);
    g_Wh[w][e] = hb;
    g_Wl[w][e] = __float2bfloat16(v - __bfloat162float(hb));
}

__global__ void gpartial0_kernel(const float* __restrict__ U) {
    int tx = threadIdx.x, bid = blockIdx.x;
    int d = tx & 127, kb = (tx >> 7) * 8;
    float f[8];
#pragma unroll
    for (int k = 0; k < 8; k++) f[k] = 0.f;
    int row0 = bid * 128;
    int rmax = min(128, NN - row0);
    for (int r = 0; r < rmax; r++) {
        int n = row0 + r;
        float yv = g_Y[n * DD + d];
#pragma unroll
        for (int k = 0; k < 8; k++) f[k] = fmaf(__ldg(&U[n * KE + kb + k]), yv, f[k]);
    }
#pragma unroll
    for (int k = 0; k < 8; k++) g_part[bid * (KE * DD) + (kb + k) * DD + d] = f[k];
}

// two-stage reduction (proven ~16 us total), deterministic fixed order
__global__ void greduceA_kernel() {
    int e = (blockIdx.x & 7) * 256 + threadIdx.x;
    int bc = blockIdx.x >> 3;
    int b0 = bc * 98, b1 = min(NB, b0 + 98);
    float s0 = 0.f, s1 = 0.f, s2 = 0.f, s3 = 0.f;
    int b = b0;
    for (; b + 4 <= b1; b += 4) {
        s0 += g_part[(b + 0) * (KE * DD) + e];
        s1 += g_part[(b + 1) * (KE * DD) + e];
        s2 += g_part[(b + 2) * (KE * DD) + e];
        s3 += g_part[(b + 3) * (KE * DD) + e];
    }
    for (; b < b1; ++b) s0 += g_part[b * (KE * DD) + e];
    g_part2[bc * (KE * DD) + e] = (s0 + s1) + (s2 + s3);
}

__global__ void greduceB_kernel(const float* __restrict__ Wt,
                                const float* __restrict__ bt, float t) {
    int e = blockIdx.x * blockDim.x + threadIdx.x;
    float s = 0.f;
#pragma unroll
    for (int c = 0; c < 8; c++) s += g_part2[c * (KE * DD) + e];
    g_G[e] = s;
    if (e < DD) g_tmod[e] = tanh_fast(t * __ldg(&Wt[e]) + __ldg(&bt[e]));
}

// ---------------------------------------------------------------------------
// fused stage kernel: mma.sync bf16x3 GEMMs + gates + RK4 + partial-G.
// No fp32 Y copy: y reconstructed from bf16 hi+lo (err 2^-18). Wz+Wr staged
// together; rY goes into the freed Wr slot; A-region reused as fp32 dh/yn buf.
// ---------------------------------------------------------------------------
__global__ __launch_bounds__(THR, 1) void fused_kernel(
    const float* H, const float* __restrict__ U,
    const float* __restrict__ bz, const float* __restrict__ br,
    const float* __restrict__ bc, const float* __restrict__ mup,
    float* Hout, int mode, float t) {
    extern __shared__ char sb[];
    char* aHi = sb + OFF_AHI;
    char* aLo = sb + OFF_ALO;
    char* w1Hi = sb + OFF_W1H;
    char* w1Lo = sb + OFF_W1L;
    char* w2Hi = sb + OFF_W2H;
    char* w2Lo = sb + OFF_W2L;
    float* sU = (float*)(sb + OFF_SU);
    float* sG = (float*)(sb + OFF_SG);
    float* sYd = (float*)(sb + OFF_AHI);   // fp32 dh/yn buffer (reuses A region)
    const uint32_t baseU = smem_u32(sb);
    const uint32_t aHiU = baseU + OFF_AHI, aLoU = baseU + OFF_ALO;
    const uint32_t w1HiU = baseU + OFF_W1H, w1LoU = baseU + OFF_W1L;
    const uint32_t w2HiU = baseU + OFF_W2H, w2LoU = baseU + OFF_W2L;

    const int tx = threadIdx.x;
    const int w = tx >> 5, lid = tx & 31;
    const int wm = (w >> 2) * 32, wn = (w & 3) * 32;
    const int bid = blockIdx.x, row0 = bid * 128;

    // ---- load Y -> aHi/aLo bf16; sU; sG; stage Wz->W1, Wr->W2 ----
#pragma unroll
    for (int it = 0; it < 8; ++it) {
        int idx = tx + THR * it;
        int r = idx >> 5, q = idx & 31;
        int n = row0 + r;
        float4 v = make_float4(0.f, 0.f, 0.f, 0.f);
        if (n < NN) v = reinterpret_cast<const float4*>(g_Y)[n * 32 + q];
        char* p = aHi + (r * SA + q * 4) * 2;
        char* pl = aLo + (r * SA + q * 4) * 2;
        *reinterpret_cast<unsigned*>(p) = pack2(v.x, v.y);
        *reinterpret_cast<unsigned*>(p + 4) = pack2(v.z, v.w);
        *reinterpret_cast<unsigned*>(pl) = pack2(v.x - bfhi(v.x), v.y - bfhi(v.y));
        *reinterpret_cast<unsigned*>(pl + 4) = pack2(v.z - bfhi(v.z), v.w - bfhi(v.w));
    }
#pragma unroll
    for (int it = 0; it < 4; ++it) {
        int idx = tx + THR * it;
        int r = idx >> 4, k = idx & 15;
        int n = row0 + r;
        sU[r * UP + k] = (n < NN) ? __ldg(&U[n * KE + k]) : 0.f;
    }
#pragma unroll
    for (int it = 0; it < 4; ++it) {
        int idx = tx + THR * it;
        int k = idx >> 7, d = idx & 127;
        sG[k * SP + d] = g_G[idx];
    }
    stage_w(w1Hi, w1Lo, 1, tx);   // Wz -> W1
    stage_w(w2Hi, w2Lo, 0, tx);   // Wr -> W2
    __syncthreads();

    // ---- GEMM Z (A x W1) and GEMM R (A x W2), back-to-back ----
    float az[2][4][4], ar[2][4][4];
#pragma unroll
    for (int mi = 0; mi < 2; mi++)
#pragma unroll
        for (int nj = 0; nj < 4; nj++)
#pragma unroll
            for (int c = 0; c < 4; c++) { az[mi][nj][c] = 0.f; ar[mi][nj][c] = 0.f; }
    gemm3(aHiU, aLoU, w1HiU, w1LoU, wm, wn, lid, az);
    gemm3(aHiU, aLoU, w2HiU, w2LoU, wm, wn, lid, ar);

    // gate z; gate r -> rY (y reconstructed from hi/lo)
#pragma unroll
    for (int mi = 0; mi < 2; mi++)
#pragma unroll
        for (int nj = 0; nj < 4; nj++) {
            int c0 = wn + nj * 8 + (lid & 3) * 2;
#pragma unroll
            for (int hh = 0; hh < 2; hh++) {
                int row = wm + mi * 16 + (lid >> 2) + hh * 8;
                float2 y = yrec(aHi, aLo, row, c0);
#pragma unroll
                for (int p = 0; p < 2; p++) {
                    az[mi][nj][hh * 2 + p] =
                        1.0f - sigm(az[mi][nj][hh * 2 + p] + __ldg(&bz[c0 + p]));
                    float rv = sigm(ar[mi][nj][hh * 2 + p] + __ldg(&br[c0 + p]));
                    ar[mi][nj][hh * 2 + p] = rv * (p ? y.y : y.x);
                }
            }
        }
    __syncthreads();   // all GEMM Z/R reads of W1/W2 complete

    // ---- write rY (hi/lo) into W2 region; stage Wc -> W1 ----
#pragma unroll
    for (int mi = 0; mi < 2; mi++)
#pragma unroll
        for (int hh = 0; hh < 2; hh++) {
            int row = wm + mi * 16 + (lid >> 2) + hh * 8;
#pragma unroll
            for (int nj = 0; nj < 4; nj++) {
                int c0 = wn + nj * 8 + (lid & 3) * 2;
                float v0 = ar[mi][nj][hh * 2], v1 = ar[mi][nj][hh * 2 + 1];
                *reinterpret_cast<unsigned*>(w2Hi + (row * SA + c0) * 2) = pack2(v0, v1);
                *reinterpret_cast<unsigned*>(w2Lo + (row * SA + c0) * 2) =
                    pack2(v0 - bfhi(v0), v1 - bfhi(v1));
            }
        }
    stage_w(w1Hi, w1Lo, 2, tx);   // Wc -> W1
    __syncthreads();

    // ---- GEMM C: ac = rY (W2 region as A) x Wc (W1) ----
    float ac[2][4][4];
#pragma unroll
    for (int mi = 0; mi < 2; mi++)
#pragma unroll
        for (int nj = 0; nj < 4; nj++)
#pragma unroll
            for (int c = 0; c < 4; c++) ac[mi][nj][c] = 0.f;
    gemm3(w2HiU, w2LoU, w1HiU, w1LoU, wm, wn, lid, ac);

    // ---- gating + spectral + dh in regs (A/Y tile still intact) ----
    {
        float mu = __ldg(mup);
#pragma unroll
        for (int mi = 0; mi < 2; mi++)
#pragma unroll
            for (int hh = 0; hh < 2; hh++) {
                int row = wm + mi * 16 + (lid >> 2) + hh * 8;
                float u[KE];
                {
                    const float4* up = reinterpret_cast<const float4*>(&sU[row * UP]);
#pragma unroll
                    for (int q = 0; q < 4; q++) {
                        float4 uv = up[q];
                        u[q * 4 + 0] = uv.x; u[q * 4 + 1] = uv.y;
                        u[q * 4 + 2] = uv.z; u[q * 4 + 3] = uv.w;
                    }
                }
#pragma unroll
                for (int nj = 0; nj < 4; nj++) {
                    int c0 = wn + nj * 8 + (lid & 3) * 2;
                    float s0 = 0.f, s1 = 0.f;
#pragma unroll
                    for (int k = 0; k < KE; k++) {
                        float2 g = *reinterpret_cast<const float2*>(&sG[k * SP + c0]);
                        s0 = fmaf(u[k], g.x, s0);
                        s1 = fmaf(u[k], g.y, s1);
                    }
                    float2 y = yrec(aHi, aLo, row, c0);
#pragma unroll
                    for (int p = 0; p < 2; p++) {
                        int d = c0 + p;
                        float yv = p ? y.y : y.x;
                        float sv = p ? s1 : s0;
                        float tmv = __ldg(&g_tmod[d]);
                        float cq = tanh_fast(ac[mi][nj][hh * 2 + p] + __ldg(&bc[d]));
                        float ozv = az[mi][nj][hh * 2 + p];
                        ac[mi][nj][hh * 2 + p] =
                            ozv * (cq + tmv - yv) - mu * (yv - sv);
                    }
                }
            }
    }
    __syncthreads();   // all y reads of A done; A region becomes fp32 dh buffer

    // ---- write dh fp32 into sYd (float2, exclusive slots) ----
#pragma unroll
    for (int mi = 0; mi < 2; mi++)
#pragma unroll
        for (int hh = 0; hh < 2; hh++) {
            int row = wm + mi * 16 + (lid >> 2) + hh * 8;
#pragma unroll
            for (int nj = 0; nj < 4; nj++) {
                int c0 = wn + nj * 8 + (lid & 3) * 2;
                *reinterpret_cast<float2*>(&sYd[row * SP + c0]) =
                    make_float2(ac[mi][nj][hh * 2], ac[mi][nj][hh * 2 + 1]);
            }
        }
    __syncthreads();

    // ---- coalesced RK4 epilogue; Y_next back into sYd for partial-G ----
#pragma unroll
    for (int it = 0; it < 8; ++it) {
        int idx = tx + THR * it;
        int r = idx >> 5, q = idx & 31;
        int n = row0 + r;
        float4 kv = *reinterpret_cast<float4*>(&sYd[r * SP + q * 4]);
        float4 yn = make_float4(0.f, 0.f, 0.f, 0.f);
        if (n < NN) {
            int g = n * 32 + q;
            float4 h4 = reinterpret_cast<const float4*>(H)[g];
            if (mode == 0) {
                reinterpret_cast<float4*>(g_acc)[g] = kv;
                yn.x = fmaf(0.05f, kv.x, h4.x); yn.y = fmaf(0.05f, kv.y, h4.y);
                yn.z = fmaf(0.05f, kv.z, h4.z); yn.w = fmaf(0.05f, kv.w, h4.w);
            } else if (mode < 3) {
                float4 a4 = reinterpret_cast<float4*>(g_acc)[g];
                a4.x += 2.f * kv.x; a4.y += 2.f * kv.y;
                a4.z += 2.f * kv.z; a4.w += 2.f * kv.w;
                reinterpret_cast<float4*>(g_acc)[g] = a4;
                float cy = (mode == 1) ? 0.05f : 0.1f;
                yn.x = fmaf(cy, kv.x, h4.x); yn.y = fmaf(cy, kv.y, h4.y);
                yn.z = fmaf(cy, kv.z, h4.z); yn.w = fmaf(cy, kv.w, h4.w);
            } else {
                float4 a4 = reinterpret_cast<float4*>(g_acc)[g];
                const float c6 = DTS / 6.0f;
                yn.x = fmaf(c6, a4.x + kv.x, h4.x);
                yn.y = fmaf(c6, a4.y + kv.y, h4.y);
                yn.z = fmaf(c6, a4.z + kv.z, h4.z);
                yn.w = fmaf(c6, a4.w + kv.w, h4.w);
                reinterpret_cast<float4*>(Hout)[g] = yn;
            }
            reinterpret_cast<float4*>(g_Y)[g] = yn;
        }
        *reinterpret_cast<float4*>(&sYd[r * SP + q * 4]) = yn;
    }
    __syncthreads();

    // ---- fused partial G for next stage (broadcast u via LDS.128) ----
    {
        int d = tx & 127, kb = (tx >> 7) * 4;
        float4 f = make_float4(0.f, 0.f, 0.f, 0.f);
#pragma unroll 4
        for (int r = 0; r < 128; r++) {
            float yv = sYd[r * SP + d];
            float4 u4 = *reinterpret_cast<const float4*>(&sU[r * UP + kb]);
            f.x = fmaf(u4.x, yv, f.x);
            f.y = fmaf(u4.y, yv, f.y);
            f.z = fmaf(u4.z, yv, f.z);
            f.w = fmaf(u4.w, yv, f.w);
        }
        float* gp = &g_part[bid * (KE * DD)];
        gp[(kb + 0) * DD + d] = f.x;
        gp[(kb + 1) * DD + d] = f.y;
        gp[(kb + 2) * DD + d] = f.z;
        gp[(kb + 3) * DD + d] = f.w;
    }
}

// ---------------------------------------------------------------------------
extern "C" void kernel_launch(void* const* d_in, const int* in_sizes, int n_in,
                              void* d_out, int out_size) {
    const float* h0 = (const float*)d_in[0];
    const float* U  = (const float*)d_in[1];
    const float* Wz = (const float*)d_in[2];
    const float* bz = (const float*)d_in[3];
    const float* Wr = (const float*)d_in[4];
    const float* br = (const float*)d_in[5];
    const float* Wc = (const float*)d_in[6];
    const float* bc = (const float*)d_in[7];
    const float* Wt = (const float*)d_in[8];
    const float* bt = (const float*)d_in[9];
    const float* mu = (const float*)d_in[10];
    float* H = (float*)d_out;

    cudaError_t rc = cudaFuncSetAttribute(
        fused_kernel, cudaFuncAttributeMaxDynamicSharedMemorySize, SMEM_BYTES);
    (void)rc;

    initcopy_kernel<<<(NN * DD / 4 + 255) / 256, 256>>>(h0, H);
    wprep_kernel<<<(3 * DD * DD + 511) / 512, 512>>>(Wr, Wz, Wc);
    gpartial0_kernel<<<NB, 256>>>(U);

    for (int i = 0; i < 10; i++) {
        float tb = (float)i * DTS;
        float ts[4] = {tb, tb + 0.05f, tb + 0.05f, tb + 0.1f};
        for (int s = 0; s < 4; s++) {
            greduceA_kernel<<<64, 256>>>();
            greduceB_kernel<<<8, 256>>>(Wt, bt, ts[s]);
            fused_kernel<<<NB, THR, SMEM_BYTES>>>(H, U, bz, br, bc, mu,
                                                  H, s, ts[s]);
        }
    }
}